// round 13
// baseline (speedup 1.0000x reference)
#include <cuda_runtime.h>
#include <cuda_fp16.h>
#include <cstdint>

#define N_USERS 60000
#define M_ITEMS 40000
#define NNODES  100000
#define D       64
#define NLAYERS 3
#define BSZ     1024
#define NEG     0.2f
#define EDGE_MAX 6400000
#define SCAN_NB 99
#define SA      72            // half-element stride for SMEM tiles (conflict-free)

// Scratch
__device__ __align__(16) float   g_x[NNODES * D];            // fp32 features
__device__ __align__(16) __half2 g_xh[NNODES * (D / 2)];     // fp16 mirror (SpMM gather)
__device__ __align__(16) __half2 g_lieh[NNODES * (D / 2)];   // fp16 lie
__device__ __align__(16) __half2 g_prodh[NNODES * (D / 2)];  // fp16 x*lie
__device__ __align__(16) int2    g_edges[EDGE_MAX];          // (col*32, val bits)
__device__ int g_cnt[NNODES];
__device__ int g_cur[NNODES];
__device__ int g_rowstart[NNODES + 1];
__device__ int g_bsum[SCAN_NB];
__device__ int g_boff[SCAN_NB];

// ---------------------------------------------------------------------------
// x0 = concat(embed_user, embed_item); fill fp16 mirror
// ---------------------------------------------------------------------------
__global__ void init_x_kernel(const float* __restrict__ eu, const float* __restrict__ ei) {
    int t = blockIdx.x * blockDim.x + threadIdx.x;
    const int total = NNODES * D / 4;
    if (t >= total) return;
    const int uElems = N_USERS * D / 4;
    float4 v = (t < uElems) ? ((const float4*)eu)[t] : ((const float4*)ei)[t - uElems];
    ((float4*)g_x)[t] = v;
    g_xh[t * 2 + 0] = __floats2half2_rn(v.x, v.y);
    g_xh[t * 2 + 1] = __floats2half2_rn(v.z, v.w);
}

// ---------------------------------------------------------------------------
// CSR build (rows padded to multiples of 16)
// ---------------------------------------------------------------------------
__global__ void zero_cnt_kernel() {
    int t = blockIdx.x * blockDim.x + threadIdx.x;
    if (t < NNODES) { g_cnt[t] = 0; g_cur[t] = 0; }
}

__global__ void hist_kernel(const int* __restrict__ er, int nnz) {
    int e = blockIdx.x * blockDim.x + threadIdx.x;
    if (e < nnz) atomicAdd(&g_cnt[er[e]], 1);
}

__global__ void scan_block_kernel() {
    __shared__ int sd[1024];
    int i = blockIdx.x * 1024 + threadIdx.x;
    int v = 0;
    if (i < NNODES) v = (g_cnt[i] + 15) & ~15;
    sd[threadIdx.x] = v;
    __syncthreads();
    #pragma unroll
    for (int off = 1; off < 1024; off <<= 1) {
        int t = (threadIdx.x >= off) ? sd[threadIdx.x - off] : 0;
        __syncthreads();
        sd[threadIdx.x] += t;
        __syncthreads();
    }
    if (i <= NNODES) g_rowstart[i] = sd[threadIdx.x] - v;
    if (threadIdx.x == 1023) g_bsum[blockIdx.x] = sd[1023];
}

__global__ void scan_top_kernel() {
    __shared__ int sd[128];
    int v = (threadIdx.x < SCAN_NB) ? g_bsum[threadIdx.x] : 0;
    sd[threadIdx.x] = v;
    __syncthreads();
    #pragma unroll
    for (int off = 1; off < 128; off <<= 1) {
        int t = (threadIdx.x >= off) ? sd[threadIdx.x - off] : 0;
        __syncthreads();
        sd[threadIdx.x] += t;
        __syncthreads();
    }
    if (threadIdx.x < SCAN_NB) g_boff[threadIdx.x] = sd[threadIdx.x] - v;
}

__global__ void scan_add_kernel() {
    int i = blockIdx.x * blockDim.x + threadIdx.x;
    if (i <= NNODES) g_rowstart[i] += g_boff[i >> 10];
}

__global__ void scatter_kernel(const int* __restrict__ er, const int* __restrict__ ec,
                               const float* __restrict__ ev, int nnz) {
    int e = blockIdx.x * blockDim.x + threadIdx.x;
    if (e >= nnz) return;
    int r = er[e];
    int pos = g_rowstart[r] + atomicAdd(&g_cur[r], 1);
    g_edges[pos] = make_int2(ec[e] * 32, __float_as_int(ev[e]));   // premultiplied col
}

// Fill each row's padding tail (col=0, val=0). Pad region < 16 entries.
__global__ void pad_kernel() {
    int row = blockIdx.x * 8 + (threadIdx.x >> 5);
    if (row >= NNODES) return;
    int lane = threadIdx.x & 31;
    int cnt = g_cnt[row];
    int pad = ((cnt + 15) & ~15) - cnt;
    if (lane < pad) g_edges[g_rowstart[row] + cnt + lane] = make_int2(0, 0);
}

// ---------------------------------------------------------------------------
// SpMM over padded CSR (pad=16): one FULL warp per row, lane owns one half2.
// Double-buffered 32-edge staging: chunk c+1 prefetched into registers while
// chunk c is consumed from SMEM -> edge-stream L2 latency hidden.
// fp16 gather payload, fp32 accumulate. Epilogue emits fp16 lie / x*lie.
// ---------------------------------------------------------------------------
__global__ __launch_bounds__(256) void spmm_csr_kernel() {
    __shared__ int2 sed[8][2][32];
    int warp = threadIdx.x >> 5;
    int lane = threadIdx.x & 31;
    int row = blockIdx.x * 8 + warp;
    if (row >= NNODES) return;
    int start = g_rowstart[row];
    int len   = g_rowstart[row + 1] - start;
    float2 acc = make_float2(0.f, 0.f);
    const int2* ep = g_edges + start;

    int nfull = len >> 5;          // 32-edge blocks
    int buf = 0;
    int2 reg;
    if (nfull > 0) reg = ep[lane];
    for (int c = 0; c < nfull; c++) {
        sed[warp][buf][lane] = reg;
        __syncwarp();
        if (c + 1 < nfull) reg = ep[((c + 1) << 5) + lane];
        #pragma unroll
        for (int k = 0; k < 32; k++) {
            int2 e = sed[warp][buf][k];
            float2 xf = __half22float2(g_xh[(size_t)(unsigned)e.x + lane]);
            float v = __int_as_float(e.y);
            acc.x += v * xf.x;
            acc.y += v * xf.y;
        }
        buf ^= 1;
    }
    if (len & 16) {                // one 16-edge tail
        __syncwarp();
        if (lane < 16) sed[warp][buf][lane] = ep[(nfull << 5) + lane];
        __syncwarp();
        #pragma unroll
        for (int k = 0; k < 16; k++) {
            int2 e = sed[warp][buf][k];
            float2 xf = __half22float2(g_xh[(size_t)(unsigned)e.x + lane]);
            float v = __int_as_float(e.y);
            acc.x += v * xf.x;
            acc.y += v * xf.y;
        }
    }

    float2 xv = *(const float2*)(g_x + (size_t)row * D + lane * 2);
    g_lieh[(size_t)row * (D / 2) + lane]  = __floats2half2_rn(acc.x, acc.y);
    g_prodh[(size_t)row * (D / 2) + lane] = __floats2half2_rn(acc.x * xv.x, acc.y * xv.y);
}

// ---------------------------------------------------------------------------
// Transform via tensor cores (mma.m16n8k16, fp32 accumulate), in place.
// ---------------------------------------------------------------------------
#define TR_SMEM_BYTES (2 * 128 * SA * 2 + 2 * 64 * SA * 2 + 64 * 4)

__device__ __forceinline__ void mma_16816(float* c, uint32_t a0, uint32_t a1,
                                          uint32_t a2, uint32_t a3,
                                          uint32_t b0, uint32_t b1) {
    asm volatile(
        "mma.sync.aligned.m16n8k16.row.col.f32.f16.f16.f32 "
        "{%0,%1,%2,%3}, {%4,%5,%6,%7}, {%8,%9}, {%0,%1,%2,%3};"
        : "+f"(c[0]), "+f"(c[1]), "+f"(c[2]), "+f"(c[3])
        : "r"(a0), "r"(a1), "r"(a2), "r"(a3), "r"(b0), "r"(b1));
}

__global__ __launch_bounds__(256) void transform_mma_kernel(
        const float* __restrict__ W1, const float* __restrict__ W2,
        const float* __restrict__ b1, const float* __restrict__ b2) {
    extern __shared__ __half sh[];
    __half* As1 = sh;                    // [128][SA]
    __half* As2 = As1 + 128 * SA;        // [128][SA]
    __half* Wt1 = As2 + 128 * SA;        // [64][SA]  W transposed: [n][k]
    __half* Wt2 = Wt1 + 64 * SA;
    float*  bs  = (float*)(Wt2 + 64 * SA);

    int tid = threadIdx.x;
    int node0 = blockIdx.x * 128;

    __half2* As1_2 = (__half2*)As1;      // row stride SA/2 = 36
    __half2* As2_2 = (__half2*)As2;
    for (int i = tid; i < 128 * 32; i += 256) {
        int m = i >> 5, j = i & 31;
        int node = node0 + m;
        __half2 l = __float2half2_rn(0.f), p = l;
        if (node < NNODES) {
            l = g_lieh[(size_t)node * 32 + j];
            p = g_prodh[(size_t)node * 32 + j];
        }
        As1_2[m * (SA / 2) + j] = l;
        As2_2[m * (SA / 2) + j] = p;
    }
    for (int i = tid; i < 4096; i += 256) {
        int k = i >> 6, n = i & 63;
        Wt1[n * SA + k] = __float2half_rn(W1[i]);
        Wt2[n * SA + k] = __float2half_rn(W2[i]);
    }
    if (tid < 64) bs[tid] = b1[tid] + b2[tid];
    __syncthreads();

    int wid = tid >> 5, lane = tid & 31;
    int r = lane >> 2, c = lane & 3;
    int mrow = wid * 16 + r;

    float acc[8][4];
    #pragma unroll
    for (int nt = 0; nt < 8; nt++)
        #pragma unroll
        for (int j = 0; j < 4; j++) acc[nt][j] = 0.f;

    #pragma unroll
    for (int kt = 0; kt < 4; kt++) {
        int ko = kt * 16 + c * 2;
        uint32_t a0 = *(const uint32_t*)(As1 + mrow * SA + ko);
        uint32_t a1 = *(const uint32_t*)(As1 + (mrow + 8) * SA + ko);
        uint32_t a2 = *(const uint32_t*)(As1 + mrow * SA + ko + 8);
        uint32_t a3 = *(const uint32_t*)(As1 + (mrow + 8) * SA + ko + 8);
        uint32_t e0 = *(const uint32_t*)(As2 + mrow * SA + ko);
        uint32_t e1 = *(const uint32_t*)(As2 + (mrow + 8) * SA + ko);
        uint32_t e2 = *(const uint32_t*)(As2 + mrow * SA + ko + 8);
        uint32_t e3 = *(const uint32_t*)(As2 + (mrow + 8) * SA + ko + 8);
        #pragma unroll
        for (int nt = 0; nt < 8; nt++) {
            uint32_t b0 = *(const uint32_t*)(Wt1 + (nt * 8 + r) * SA + ko);
            uint32_t b1v = *(const uint32_t*)(Wt1 + (nt * 8 + r) * SA + ko + 8);
            mma_16816(acc[nt], a0, a1, a2, a3, b0, b1v);
            uint32_t d0 = *(const uint32_t*)(Wt2 + (nt * 8 + r) * SA + ko);
            uint32_t d1 = *(const uint32_t*)(Wt2 + (nt * 8 + r) * SA + ko + 8);
            mma_16816(acc[nt], e0, e1, e2, e3, d0, d1);
        }
    }

    int m0 = node0 + mrow;
    int m1 = m0 + 8;
    #pragma unroll
    for (int nt = 0; nt < 8; nt++) {
        int n0 = nt * 8 + c * 2;
        float bx = bs[n0], by = bs[n0 + 1];
        if (m0 < NNODES) {
            float vx = acc[nt][0] + bx, vy = acc[nt][1] + by;
            vx = (vx > 0.f) ? vx : NEG * vx;
            vy = (vy > 0.f) ? vy : NEG * vy;
            *(float2*)(g_x + (size_t)m0 * D + n0) = make_float2(vx, vy);
            g_xh[(size_t)m0 * 32 + n0 / 2] = __floats2half2_rn(vx, vy);
        }
        if (m1 < NNODES) {
            float vx = acc[nt][2] + bx, vy = acc[nt][3] + by;
            vx = (vx > 0.f) ? vx : NEG * vx;
            vy = (vy > 0.f) ? vy : NEG * vy;
            *(float2*)(g_x + (size_t)m1 * D + n0) = make_float2(vx, vy);
            g_xh[(size_t)m1 * 32 + n0 / 2] = __floats2half2_rn(vx, vy);
        }
    }
}

// ---------------------------------------------------------------------------
// Gather selected rows' layer slice into d_out: [3][B][4*D]
// ---------------------------------------------------------------------------
__global__ void gather_kernel(const int* __restrict__ users, const int* __restrict__ obs,
                              const int* __restrict__ unobs, float* __restrict__ out,
                              int layer) {
    int t = blockIdx.x * blockDim.x + threadIdx.x;
    if (t >= 3 * BSZ * (D / 4)) return;
    int j4 = t & 15;
    int b  = (t >> 4) & (BSZ - 1);
    int g  = t >> 14;
    int node = (g == 0) ? users[b] : ((g == 1) ? N_USERS + obs[b] : N_USERS + unobs[b]);
    float4 v = *(const float4*)(g_x + (size_t)node * D + j4 * 4);
    *(float4*)(out + (size_t)(g * BSZ + b) * (4 * D) + layer * D + j4 * 4) = v;
}

// ---------------------------------------------------------------------------
extern "C" void kernel_launch(void* const* d_in, const int* in_sizes, int n_in,
                              void* d_out, int out_size) {
    const int*   er = (const int*)d_in[0];
    const int*   ec = (const int*)d_in[1];
    const float* ev = (const float*)d_in[2];
    const float* eu = (const float*)d_in[3];
    const float* ei = (const float*)d_in[4];
    const float* W1 = (const float*)d_in[5];
    const float* W2 = (const float*)d_in[6];
    const float* b1 = (const float*)d_in[7];
    const float* b2 = (const float*)d_in[8];
    const int*   su = (const int*)d_in[9];
    const int*   oi = (const int*)d_in[10];
    const int*   ui = (const int*)d_in[11];
    float* out = (float*)d_out;
    int nnz = in_sizes[0];

    cudaFuncSetAttribute(transform_mma_kernel,
                         cudaFuncAttributeMaxDynamicSharedMemorySize, TR_SMEM_BYTES);

    const int cpBlocks = (NNODES * D / 4 + 255) / 256;
    const int gBlocks  = (3 * BSZ * (D / 4) + 255) / 256;
    const int eBlocks  = (nnz + 255) / 256;
    const int rwBlocks = (NNODES + 7) / 8;     // warp-per-row kernels
    const int trBlocks = (NNODES + 127) / 128;

    // CSR build
    zero_cnt_kernel<<<(NNODES + 255) / 256, 256>>>();
    hist_kernel<<<eBlocks, 256>>>(er, nnz);
    scan_block_kernel<<<SCAN_NB, 1024>>>();
    scan_top_kernel<<<1, 128>>>();
    scan_add_kernel<<<(NNODES + 256) / 256, 256>>>();
    scatter_kernel<<<eBlocks, 256>>>(er, ec, ev, nnz);
    pad_kernel<<<rwBlocks, 256>>>();

    init_x_kernel<<<cpBlocks, 256>>>(eu, ei);
    gather_kernel<<<gBlocks, 256>>>(su, oi, ui, out, 0);

    for (int i = 0; i < NLAYERS; i++) {
        spmm_csr_kernel<<<rwBlocks, 256>>>();
        transform_mma_kernel<<<trBlocks, 256, TR_SMEM_BYTES>>>(
            W1 + (size_t)i * D * D, W2 + (size_t)i * D * D,
            b1 + (size_t)i * D,     b2 + (size_t)i * D);
        gather_kernel<<<gBlocks, 256>>>(su, oi, ui, out, i + 1);
    }
}

// round 15
// speedup vs baseline: 1.1418x; 1.1418x over previous
#include <cuda_runtime.h>
#include <cuda_fp16.h>
#include <cstdint>

#define N_USERS 60000
#define M_ITEMS 40000
#define NNODES  100000
#define D       64
#define NLAYERS 3
#define BSZ     1024
#define NEG     0.2f
#define EDGE_MAX 6400000
#define SCAN_NB 99
#define SA      72            // half-element stride for SMEM tiles (conflict-free)

// Scratch
__device__ __align__(16) float   g_x[NNODES * D];            // fp32 features
__device__ __align__(16) __half2 g_xh[NNODES * (D / 2)];     // fp16 mirror (SpMM gather)
__device__ __align__(16) __half2 g_lieh[NNODES * (D / 2)];   // fp16 lie
__device__ __align__(16) __half2 g_prodh[NNODES * (D / 2)];  // fp16 x*lie
__device__ __align__(16) int2    g_edges[EDGE_MAX];          // (col*32, val bits)
__device__ int g_cnt[NNODES];
__device__ int g_cur[NNODES];
__device__ int g_rowstart[NNODES + 1];
__device__ int g_bsum[SCAN_NB];
__device__ int g_boff[SCAN_NB];

// ---------------------------------------------------------------------------
// x0 = concat(embed_user, embed_item); fill fp16 mirror
// ---------------------------------------------------------------------------
__global__ void init_x_kernel(const float* __restrict__ eu, const float* __restrict__ ei) {
    int t = blockIdx.x * blockDim.x + threadIdx.x;
    const int total = NNODES * D / 4;
    if (t >= total) return;
    const int uElems = N_USERS * D / 4;
    float4 v = (t < uElems) ? ((const float4*)eu)[t] : ((const float4*)ei)[t - uElems];
    ((float4*)g_x)[t] = v;
    g_xh[t * 2 + 0] = __floats2half2_rn(v.x, v.y);
    g_xh[t * 2 + 1] = __floats2half2_rn(v.z, v.w);
}

// ---------------------------------------------------------------------------
// CSR build (rows padded to multiples of 16)
// ---------------------------------------------------------------------------
__global__ void zero_cnt_kernel() {
    int t = blockIdx.x * blockDim.x + threadIdx.x;
    if (t < NNODES) { g_cnt[t] = 0; g_cur[t] = 0; }
}

__global__ void hist_kernel(const int* __restrict__ er, int nnz) {
    int e = blockIdx.x * blockDim.x + threadIdx.x;
    if (e < nnz) atomicAdd(&g_cnt[er[e]], 1);
}

__global__ void scan_block_kernel() {
    __shared__ int sd[1024];
    int i = blockIdx.x * 1024 + threadIdx.x;
    int v = 0;
    if (i < NNODES) v = (g_cnt[i] + 15) & ~15;
    sd[threadIdx.x] = v;
    __syncthreads();
    #pragma unroll
    for (int off = 1; off < 1024; off <<= 1) {
        int t = (threadIdx.x >= off) ? sd[threadIdx.x - off] : 0;
        __syncthreads();
        sd[threadIdx.x] += t;
        __syncthreads();
    }
    if (i <= NNODES) g_rowstart[i] = sd[threadIdx.x] - v;
    if (threadIdx.x == 1023) g_bsum[blockIdx.x] = sd[1023];
}

__global__ void scan_top_kernel() {
    __shared__ int sd[128];
    int v = (threadIdx.x < SCAN_NB) ? g_bsum[threadIdx.x] : 0;
    sd[threadIdx.x] = v;
    __syncthreads();
    #pragma unroll
    for (int off = 1; off < 128; off <<= 1) {
        int t = (threadIdx.x >= off) ? sd[threadIdx.x - off] : 0;
        __syncthreads();
        sd[threadIdx.x] += t;
        __syncthreads();
    }
    if (threadIdx.x < SCAN_NB) g_boff[threadIdx.x] = sd[threadIdx.x] - v;
}

__global__ void scan_add_kernel() {
    int i = blockIdx.x * blockDim.x + threadIdx.x;
    if (i <= NNODES) g_rowstart[i] += g_boff[i >> 10];
}

__global__ void scatter_kernel(const int* __restrict__ er, const int* __restrict__ ec,
                               const float* __restrict__ ev, int nnz) {
    int e = blockIdx.x * blockDim.x + threadIdx.x;
    if (e >= nnz) return;
    int r = er[e];
    int pos = g_rowstart[r] + atomicAdd(&g_cur[r], 1);
    g_edges[pos] = make_int2(ec[e] * 32, __float_as_int(ev[e]));   // premultiplied col
}

// Fill each row's padding tail (col=0, val=0). Pad region < 16 entries.
__global__ void pad_kernel() {
    int row = blockIdx.x * 8 + (threadIdx.x >> 5);
    if (row >= NNODES) return;
    int lane = threadIdx.x & 31;
    int cnt = g_cnt[row];
    int pad = ((cnt + 15) & ~15) - cnt;
    if (lane < pad) g_edges[g_rowstart[row] + cnt + lane] = make_int2(0, 0);
}

// ---------------------------------------------------------------------------
// SpMM over padded CSR (pad=16): one FULL warp per row, TWO edges per
// iteration (lanes 0-15 -> edge 2k, lanes 16-31 -> edge 2k+1), each lane
// gathers 4 features with one LDG.64. Halves LSU ops per edge vs the
// one-edge-per-iteration form. Warp-uniform trip count (no divergence).
// fp16 gather payload, fp32 accumulate. Epilogue emits fp16 lie / x*lie.
// ---------------------------------------------------------------------------
__global__ __launch_bounds__(256) void spmm_csr_kernel() {
    __shared__ int2 sed[8][32];
    int warp = threadIdx.x >> 5;
    int lane = threadIdx.x & 31;
    int half = lane >> 4;        // 0: even edge of pair, 1: odd edge
    int l16  = lane & 15;
    int row = blockIdx.x * 8 + warp;
    if (row >= NNODES) return;
    int start = g_rowstart[row];
    int len   = g_rowstart[row + 1] - start;
    const int2* ep = g_edges + start;
    const __half2* xh = g_xh;
    float4 acc = make_float4(0.f, 0.f, 0.f, 0.f);

    int nfull = len >> 5;          // 32-edge blocks
    for (int c = 0; c < nfull; c++) {
        sed[warp][lane] = ep[(c << 5) + lane];
        __syncwarp();
        #pragma unroll
        for (int k = 0; k < 16; k++) {
            int2 e = sed[warp][2 * k + half];
            float v = __int_as_float(e.y);
            int2 xr = *(const int2*)(xh + (size_t)(unsigned)e.x + l16 * 2);
            float2 f0 = __half22float2(*(__half2*)&xr.x);
            float2 f1 = __half22float2(*(__half2*)&xr.y);
            acc.x += v * f0.x;
            acc.y += v * f0.y;
            acc.z += v * f1.x;
            acc.w += v * f1.y;
        }
        __syncwarp();
    }
    if (len & 16) {                // one 16-edge tail (8 pairs)
        if (lane < 16) sed[warp][lane] = ep[(nfull << 5) + lane];
        __syncwarp();
        #pragma unroll
        for (int k = 0; k < 8; k++) {
            int2 e = sed[warp][2 * k + half];
            float v = __int_as_float(e.y);
            int2 xr = *(const int2*)(xh + (size_t)(unsigned)e.x + l16 * 2);
            float2 f0 = __half22float2(*(__half2*)&xr.x);
            float2 f1 = __half22float2(*(__half2*)&xr.y);
            acc.x += v * f0.x;
            acc.y += v * f0.y;
            acc.z += v * f1.x;
            acc.w += v * f1.y;
        }
    }

    // Combine even/odd halves: lane l += lane l+16.
    acc.x += __shfl_down_sync(0xffffffffu, acc.x, 16);
    acc.y += __shfl_down_sync(0xffffffffu, acc.y, 16);
    acc.z += __shfl_down_sync(0xffffffffu, acc.z, 16);
    acc.w += __shfl_down_sync(0xffffffffu, acc.w, 16);

    if (lane < 16) {
        float4 xv = *(const float4*)(g_x + (size_t)row * D + l16 * 4);
        __half2 h0 = __floats2half2_rn(acc.x, acc.y);
        __half2 h1 = __floats2half2_rn(acc.z, acc.w);
        *(int2*)(g_lieh + (size_t)row * 32 + l16 * 2) =
            make_int2(*(int*)&h0, *(int*)&h1);
        __half2 p0 = __floats2half2_rn(acc.x * xv.x, acc.y * xv.y);
        __half2 p1 = __floats2half2_rn(acc.z * xv.z, acc.w * xv.w);
        *(int2*)(g_prodh + (size_t)row * 32 + l16 * 2) =
            make_int2(*(int*)&p0, *(int*)&p1);
    }
}

// ---------------------------------------------------------------------------
// Transform via tensor cores (mma.m16n8k16, fp32 accumulate), in place.
// ---------------------------------------------------------------------------
#define TR_SMEM_BYTES (2 * 128 * SA * 2 + 2 * 64 * SA * 2 + 64 * 4)

__device__ __forceinline__ void mma_16816(float* c, uint32_t a0, uint32_t a1,
                                          uint32_t a2, uint32_t a3,
                                          uint32_t b0, uint32_t b1) {
    asm volatile(
        "mma.sync.aligned.m16n8k16.row.col.f32.f16.f16.f32 "
        "{%0,%1,%2,%3}, {%4,%5,%6,%7}, {%8,%9}, {%0,%1,%2,%3};"
        : "+f"(c[0]), "+f"(c[1]), "+f"(c[2]), "+f"(c[3])
        : "r"(a0), "r"(a1), "r"(a2), "r"(a3), "r"(b0), "r"(b1));
}

__global__ __launch_bounds__(256) void transform_mma_kernel(
        const float* __restrict__ W1, const float* __restrict__ W2,
        const float* __restrict__ b1, const float* __restrict__ b2) {
    extern __shared__ __half sh[];
    __half* As1 = sh;                    // [128][SA]
    __half* As2 = As1 + 128 * SA;        // [128][SA]
    __half* Wt1 = As2 + 128 * SA;        // [64][SA]  W transposed: [n][k]
    __half* Wt2 = Wt1 + 64 * SA;
    float*  bs  = (float*)(Wt2 + 64 * SA);

    int tid = threadIdx.x;
    int node0 = blockIdx.x * 128;

    __half2* As1_2 = (__half2*)As1;      // row stride SA/2 = 36
    __half2* As2_2 = (__half2*)As2;
    for (int i = tid; i < 128 * 32; i += 256) {
        int m = i >> 5, j = i & 31;
        int node = node0 + m;
        __half2 l = __float2half2_rn(0.f), p = l;
        if (node < NNODES) {
            l = g_lieh[(size_t)node * 32 + j];
            p = g_prodh[(size_t)node * 32 + j];
        }
        As1_2[m * (SA / 2) + j] = l;
        As2_2[m * (SA / 2) + j] = p;
    }
    for (int i = tid; i < 4096; i += 256) {
        int k = i >> 6, n = i & 63;
        Wt1[n * SA + k] = __float2half_rn(W1[i]);
        Wt2[n * SA + k] = __float2half_rn(W2[i]);
    }
    if (tid < 64) bs[tid] = b1[tid] + b2[tid];
    __syncthreads();

    int wid = tid >> 5, lane = tid & 31;
    int r = lane >> 2, c = lane & 3;
    int mrow = wid * 16 + r;

    float acc[8][4];
    #pragma unroll
    for (int nt = 0; nt < 8; nt++)
        #pragma unroll
        for (int j = 0; j < 4; j++) acc[nt][j] = 0.f;

    #pragma unroll
    for (int kt = 0; kt < 4; kt++) {
        int ko = kt * 16 + c * 2;
        uint32_t a0 = *(const uint32_t*)(As1 + mrow * SA + ko);
        uint32_t a1 = *(const uint32_t*)(As1 + (mrow + 8) * SA + ko);
        uint32_t a2 = *(const uint32_t*)(As1 + mrow * SA + ko + 8);
        uint32_t a3 = *(const uint32_t*)(As1 + (mrow + 8) * SA + ko + 8);
        uint32_t e0 = *(const uint32_t*)(As2 + mrow * SA + ko);
        uint32_t e1 = *(const uint32_t*)(As2 + (mrow + 8) * SA + ko);
        uint32_t e2 = *(const uint32_t*)(As2 + mrow * SA + ko + 8);
        uint32_t e3 = *(const uint32_t*)(As2 + (mrow + 8) * SA + ko + 8);
        #pragma unroll
        for (int nt = 0; nt < 8; nt++) {
            uint32_t b0 = *(const uint32_t*)(Wt1 + (nt * 8 + r) * SA + ko);
            uint32_t b1v = *(const uint32_t*)(Wt1 + (nt * 8 + r) * SA + ko + 8);
            mma_16816(acc[nt], a0, a1, a2, a3, b0, b1v);
            uint32_t d0 = *(const uint32_t*)(Wt2 + (nt * 8 + r) * SA + ko);
            uint32_t d1 = *(const uint32_t*)(Wt2 + (nt * 8 + r) * SA + ko + 8);
            mma_16816(acc[nt], e0, e1, e2, e3, d0, d1);
        }
    }

    int m0 = node0 + mrow;
    int m1 = m0 + 8;
    #pragma unroll
    for (int nt = 0; nt < 8; nt++) {
        int n0 = nt * 8 + c * 2;
        float bx = bs[n0], by = bs[n0 + 1];
        if (m0 < NNODES) {
            float vx = acc[nt][0] + bx, vy = acc[nt][1] + by;
            vx = (vx > 0.f) ? vx : NEG * vx;
            vy = (vy > 0.f) ? vy : NEG * vy;
            *(float2*)(g_x + (size_t)m0 * D + n0) = make_float2(vx, vy);
            g_xh[(size_t)m0 * 32 + n0 / 2] = __floats2half2_rn(vx, vy);
        }
        if (m1 < NNODES) {
            float vx = acc[nt][2] + bx, vy = acc[nt][3] + by;
            vx = (vx > 0.f) ? vx : NEG * vx;
            vy = (vy > 0.f) ? vy : NEG * vy;
            *(float2*)(g_x + (size_t)m1 * D + n0) = make_float2(vx, vy);
            g_xh[(size_t)m1 * 32 + n0 / 2] = __floats2half2_rn(vx, vy);
        }
    }
}

// ---------------------------------------------------------------------------
// Gather selected rows' layer slice into d_out: [3][B][4*D]
// ---------------------------------------------------------------------------
__global__ void gather_kernel(const int* __restrict__ users, const int* __restrict__ obs,
                              const int* __restrict__ unobs, float* __restrict__ out,
                              int layer) {
    int t = blockIdx.x * blockDim.x + threadIdx.x;
    if (t >= 3 * BSZ * (D / 4)) return;
    int j4 = t & 15;
    int b  = (t >> 4) & (BSZ - 1);
    int g  = t >> 14;
    int node = (g == 0) ? users[b] : ((g == 1) ? N_USERS + obs[b] : N_USERS + unobs[b]);
    float4 v = *(const float4*)(g_x + (size_t)node * D + j4 * 4);
    *(float4*)(out + (size_t)(g * BSZ + b) * (4 * D) + layer * D + j4 * 4) = v;
}

// ---------------------------------------------------------------------------
extern "C" void kernel_launch(void* const* d_in, const int* in_sizes, int n_in,
                              void* d_out, int out_size) {
    const int*   er = (const int*)d_in[0];
    const int*   ec = (const int*)d_in[1];
    const float* ev = (const float*)d_in[2];
    const float* eu = (const float*)d_in[3];
    const float* ei = (const float*)d_in[4];
    const float* W1 = (const float*)d_in[5];
    const float* W2 = (const float*)d_in[6];
    const float* b1 = (const float*)d_in[7];
    const float* b2 = (const float*)d_in[8];
    const int*   su = (const int*)d_in[9];
    const int*   oi = (const int*)d_in[10];
    const int*   ui = (const int*)d_in[11];
    float* out = (float*)d_out;
    int nnz = in_sizes[0];

    cudaFuncSetAttribute(transform_mma_kernel,
                         cudaFuncAttributeMaxDynamicSharedMemorySize, TR_SMEM_BYTES);

    const int cpBlocks = (NNODES * D / 4 + 255) / 256;
    const int gBlocks  = (3 * BSZ * (D / 4) + 255) / 256;
    const int eBlocks  = (nnz + 255) / 256;
    const int rwBlocks = (NNODES + 7) / 8;     // warp-per-row kernels
    const int trBlocks = (NNODES + 127) / 128;

    // CSR build
    zero_cnt_kernel<<<(NNODES + 255) / 256, 256>>>();
    hist_kernel<<<eBlocks, 256>>>(er, nnz);
    scan_block_kernel<<<SCAN_NB, 1024>>>();
    scan_top_kernel<<<1, 128>>>();
    scan_add_kernel<<<(NNODES + 256) / 256, 256>>>();
    scatter_kernel<<<eBlocks, 256>>>(er, ec, ev, nnz);
    pad_kernel<<<rwBlocks, 256>>>();

    init_x_kernel<<<cpBlocks, 256>>>(eu, ei);
    gather_kernel<<<gBlocks, 256>>>(su, oi, ui, out, 0);

    for (int i = 0; i < NLAYERS; i++) {
        spmm_csr_kernel<<<rwBlocks, 256>>>();
        transform_mma_kernel<<<trBlocks, 256, TR_SMEM_BYTES>>>(
            W1 + (size_t)i * D * D, W2 + (size_t)i * D * D,
            b1 + (size_t)i * D,     b2 + (size_t)i * D);
        gather_kernel<<<gBlocks, 256>>>(su, oi, ui, out, i + 1);
    }
}